// round 11
// baseline (speedup 1.0000x reference)
#include <cuda_runtime.h>
#include <cuda_fp16.h>
#include <math.h>

#define DET 512
#define NB  16
#define NT  180
#define NPH 90
#define CW  768   // padded column width: detector index range [-128, 640)

// filtered sinogram, layout [b][t][d]
static __device__ float g_xf[(size_t)NB * NT * DET];
// packed pair-columns: [b][ph][i] = (half2(g_t,g_u), half2(d_t,d_u)), i in [0,768)
static __device__ uint2 g_pk[(size_t)NB * NPH * CW];

// bit-cast helpers (register moves only)
__device__ __forceinline__ unsigned int h2_to_u32(__half2 h) {
    return *reinterpret_cast<unsigned int*>(&h);
}
__device__ __forceinline__ __half2 u32_to_h2(unsigned int u) {
    return *reinterpret_cast<__half2*>(&u);
}

// ---------------------------------------------------------------------------
// Kernel 1: Ram-Lak filtering as direct convolution with closed-form kernel.
// Angle tile = 4 (180 = 45*4, no tail) -> 720 blocks for full residency.
// ---------------------------------------------------------------------------
__global__ __launch_bounds__(512) void filter_kernel(const float* __restrict__ x)
{
    const int b  = blockIdx.x;
    const int t0 = blockIdx.y * 4;
    const int tid = threadIdx.x;            // 0..511

    __shared__ __align__(16) float xs[DET][4];    // x[b][m][t0..t0+3]
    __shared__ float Gt[DET];

    {
        int k = tid;
        float v;
        if (k == 0)       v = 0.5f;
        else if (k & 1) { float fk = (float)k; v = -2.0f / (9.869604401089358f * fk * fk); }
        else              v = 0.0f;
        Gt[k] = v;
    }

    const float* xb = x + (size_t)b * DET * NT;
    const int tt = tid & 3;
    const int mb = tid >> 2;                 // 0..127
    const int tg0 = t0 + tt;                 // always < 180
    #pragma unroll
    for (int p = 0; p < 4; p++) {
        int m = mb + p * 128;
        xs[m][tt] = xb[m * NT + tg0];
    }
    __syncthreads();

    const int d = tid;
    float4 acc;
    {
        float4 v = *(const float4*)xs[d];
        acc.x = 0.5f * v.x; acc.y = 0.5f * v.y;
        acc.z = 0.5f * v.z; acc.w = 0.5f * v.w;
    }

    const int m0 = (d & 1) ^ 1;              // opposite parity of d
    for (int j = 0; j < 256; j++) {
        int m = m0 + 2 * j;
        int k = d - m; k = (k < 0) ? -k : k;
        float gv = Gt[k];
        float4 v = *(const float4*)xs[m];    // broadcast within parity class
        acc.x = fmaf(gv, v.x, acc.x);
        acc.y = fmaf(gv, v.y, acc.y);
        acc.z = fmaf(gv, v.z, acc.z);
        acc.w = fmaf(gv, v.w, acc.w);
    }

    g_xf[((size_t)b * NT + t0 + 0) * DET + d] = acc.x;
    g_xf[((size_t)b * NT + t0 + 1) * DET + d] = acc.y;
    g_xf[((size_t)b * NT + t0 + 2) * DET + d] = acc.z;
    g_xf[((size_t)b * NT + t0 + 3) * DET + d] = acc.w;
}

// ---------------------------------------------------------------------------
// Kernel 1b: repack into padded, fp16-packed pair-columns (transposed pack:
// .x = (g_t, g_u), .y = (d_t, d_u) so one HFMA2 serves both angles).
// ph=0 -> angles {0, 90}; ph in 1..89 -> angles {ph, 180-ph}.
// ---------------------------------------------------------------------------
__global__ __launch_bounds__(256) void repack_kernel()
{
    const int b  = blockIdx.x;
    const int ph = blockIdx.y;
    const int t = (ph == 0) ? 0  : ph;
    const int u = (ph == 0) ? 90 : (180 - ph);

    const float* st = g_xf + ((size_t)b * NT + t) * DET;
    const float* su = g_xf + ((size_t)b * NT + u) * DET;
    uint2* dst = g_pk + ((size_t)b * NPH + ph) * CW;

    for (int i = threadIdx.x; i < CW; i += 256) {
        int d = i - 128;
        float gt = 0.0f, dt = 0.0f, gu = 0.0f, du = 0.0f;
        if (d >= 0 && d < DET) {
            gt = st[d]; dt = ((d < DET - 1) ? st[d + 1] : 0.0f) - gt;
            gu = su[d]; du = ((d < DET - 1) ? su[d + 1] : 0.0f) - gu;
        } else if (d == -1) {
            dt = st[0]; du = su[0];
        }
        uint2 e;
        e.x = h2_to_u32(__floats2half2_rn(gt, gu));   // (g_t, g_u)
        e.y = h2_to_u32(__floats2half2_rn(dt, du));   // (d_t, d_u)
        dst[i] = e;
    }
}

// ---------------------------------------------------------------------------
// Kernel 2: backprojection, mirror-angle pairing, fp16 packed columns,
// 2 phases per barrier (45 barriers).
// ---------------------------------------------------------------------------
#define TAPIDX(iy, i0, w)                                    \
    {   float _tm = __fadd_rd((iy), MAGIC);                  \
        (i0) = __float_as_int(_tm) & 0x3FF;                  \
        (w)  = (iy) - (_tm - MAGIC); }

__global__ __launch_bounds__(256, 7) void backproj_kernel(float* __restrict__ out)
{
    const int b  = blockIdx.z;
    const int x0 = blockIdx.x * 32;          // left-half x tile [x0, x0+32)
    const int y0 = blockIdx.y * 64;          // y tile [y0, y0+64)
    const int tid = threadIdx.x;             // 0..255
    const int tx = tid & 31;
    const int ty = tid >> 5;                 // 0..7

    __shared__ __align__(16) uint2 col[2][2][CW];   // [buf][phase-in-group]
    __shared__ float2 cs[NT];

    if (tid < NT) {
        float rad = (float)tid * 0.017453292519943295f;
        float sv, cv;
        sincosf(rad, &sv, &cv);
        cs[tid] = make_float2(cv, sv);
    }

    const uint2* pkb = g_pk + (size_t)b * NPH * CW;

    // preload phases 0,1
    #pragma unroll
    for (int r = 0; r < 3; r++) {
        col[0][0][tid + r * 256] = pkb[tid + r * 256];
        col[0][1][tid + r * 256] = pkb[CW + tid + r * 256];
    }
    __syncthreads();

    float accP1[8], accP2[8];
    #pragma unroll
    for (int k = 0; k < 8; k++) { accP1[k] = 0.0f; accP2[k] = 0.0f; }

    const float fx = (float)(x0 + tx) - 255.5f;        // < 0 always
    const float fy = (float)(y0 + ty) - 255.5f;
    const float lim = 65408.0f;                        // (1 - 1/512) * 256^2
    const float MAGIC = 8388608.0f;                    // 2^23

    const float fxmin = 255.5f - (float)(x0 + 31);
    float fymin;
    {
        float lo = fy, hi = fy + 56.0f;
        fymin = (lo <= 0.0f && hi >= 0.0f) ? 0.0f : fminf(fabsf(lo), fabsf(hi));
    }
    const bool active = (fxmin * fxmin + fymin * fymin) <= lim;  // warp-uniform

    for (int pg = 0; pg < 45; pg++) {
        const int cur = pg & 1;
        // prefetch phases 2pg+2, 2pg+3 (clamped at the end; values unused)
        {
            int p2 = 2 * pg + 2; if (p2 > NPH - 1) p2 = NPH - 1;
            int p3 = 2 * pg + 3; if (p3 > NPH - 1) p3 = NPH - 1;
            const uint2* s2 = pkb + (size_t)p2 * CW;
            const uint2* s3 = pkb + (size_t)p3 * CW;
            uint2* d2 = col[cur ^ 1][0];
            uint2* d3 = col[cur ^ 1][1];
            #pragma unroll
            for (int r = 0; r < 3; r++) {
                d2[tid + r * 256] = s2[tid + r * 256];
                d3[tid + r * 256] = s3[tid + r * 256];
            }
        }

        if (active) {
            #pragma unroll
            for (int sub = 0; sub < 2; sub++) {
                const int ph = 2 * pg + sub;
                const uint2* cp = col[cur][sub];
                if (ph == 0) {
                    // angles 0 (low lane) and 90 (high lane)
                    const float2 a0 = cs[0];
                    const float2 a9 = cs[90];
                    #pragma unroll
                    for (int k = 0; k < 8; k++) {
                        float fyk = fy + 8.0f * (float)k;
                        float b0 = fmaf(-a0.y, fyk, 383.5f);
                        float b9 = fmaf(-a9.y, fyk, 383.5f);
                        float iy, w; int i0; uint2 q; __half2 v;
                        iy = fmaf(a0.x,  fx, b0); TAPIDX(iy, i0, w); q = cp[i0];
                        v = __hfma2(__float2half2_rn(w), u32_to_h2(q.y), u32_to_h2(q.x));
                        accP1[k] += __low2float(v);
                        iy = fmaf(a0.x, -fx, b0); TAPIDX(iy, i0, w); q = cp[i0];
                        v = __hfma2(__float2half2_rn(w), u32_to_h2(q.y), u32_to_h2(q.x));
                        accP2[k] += __low2float(v);
                        iy = fmaf(a9.x,  fx, b9); TAPIDX(iy, i0, w); q = cp[i0];
                        v = __hfma2(__float2half2_rn(w), u32_to_h2(q.y), u32_to_h2(q.x));
                        accP1[k] += __high2float(v);
                        iy = fmaf(a9.x, -fx, b9); TAPIDX(iy, i0, w); q = cp[i0];
                        v = __hfma2(__float2half2_rn(w), u32_to_h2(q.y), u32_to_h2(q.x));
                        accP2[k] += __high2float(v);
                    }
                } else {
                    // pair (t=ph, u=180-ph): c_u = -c, s_u = s
                    const float2 cst = cs[ph];
                    const float c = cst.x, s = cst.y;
                    const float iyA0 = fmaf(c, fx, fmaf(-s, fy, 383.5f));
                    const float D    = -2.0f * (c * fx);      // iyB = iyA + D
                    const float s8   = 8.0f * s;
                    #pragma unroll
                    for (int k = 0; k < 8; k++) {
                        float iyA = fmaf(-s8, (float)k, iyA0);
                        float iyB = iyA + D;
                        float w; int i0; uint2 q; __half2 v;
                        TAPIDX(iyA, i0, w); q = cp[i0];
                        v = __hfma2(__float2half2_rn(w), u32_to_h2(q.y), u32_to_h2(q.x));
                        accP1[k] += __low2float(v);    // (p1, t)
                        accP2[k] += __high2float(v);   // (p2, u)
                        TAPIDX(iyB, i0, w); q = cp[i0];
                        v = __hfma2(__float2half2_rn(w), u32_to_h2(q.y), u32_to_h2(q.x));
                        accP1[k] += __high2float(v);   // (p1, u)
                        accP2[k] += __low2float(v);    // (p2, t)
                    }
                }
            }
        }
        __syncthreads();
    }

    // epilogue: circle mask (mirror-exact) + pi/(2*180) scale
    const float scale = 0.008726646259971648f;   // pi/360
    float* ob = out + (size_t)b * DET * DET;
    const int x1 = x0 + tx;
    const int x2 = 511 - x1;
    #pragma unroll
    for (int k = 0; k < 8; k++) {
        int   py  = y0 + ty + 8 * k;
        float fyk = fy + 8.0f * (float)k;
        float m   = ((fx * fx + fyk * fyk) <= lim) ? scale : 0.0f;
        ob[(size_t)py * DET + x1] = accP1[k] * m;
        ob[(size_t)py * DET + x2] = accP2[k] * m;
    }
}

extern "C" void kernel_launch(void* const* d_in, const int* in_sizes, int n_in,
                              void* d_out, int out_size)
{
    const float* x = (const float*)d_in[0];
    float* out = (float*)d_out;

    dim3 gf(NB, 45);          // 16 batches x 45 angle tiles (4 angles each)
    filter_kernel<<<gf, 512>>>(x);

    dim3 gr(NB, NPH);         // pack pair-columns once per (batch, phase)
    repack_kernel<<<gr, 256>>>();

    dim3 gb(8, 8, NB);        // 8 x-tiles (left half, mirrored) x 8 y-tiles
    backproj_kernel<<<gb, 256>>>(out);
}

// round 12
// speedup vs baseline: 1.0814x; 1.0814x over previous
#include <cuda_runtime.h>
#include <cuda_fp16.h>
#include <math.h>

#define DET 512
#define NB  16
#define NT  180
#define NPH 90
#define CW  768   // padded column width: detector index range [-128, 640)

// filtered sinogram, layout [b][t][d]
static __device__ float g_xf[(size_t)NB * NT * DET];
// packed quad-columns: [b][ph][i] = (h2(gF_t,gF_u), h2(dF_t,dF_u), h2(gR_t,gR_u), h2(dR_t,dR_u))
static __device__ uint4 g_pk[(size_t)NB * NPH * CW];

__device__ __forceinline__ unsigned int h2_to_u32(__half2 h) {
    return *reinterpret_cast<unsigned int*>(&h);
}
__device__ __forceinline__ __half2 u32_to_h2(unsigned int u) {
    return *reinterpret_cast<__half2*>(&u);
}

// ---------------------------------------------------------------------------
// Kernel 1: Ram-Lak filtering as direct convolution (tile-8 version, R10 best)
// ---------------------------------------------------------------------------
__global__ __launch_bounds__(512) void filter_kernel(const float* __restrict__ x)
{
    const int b  = blockIdx.x;
    const int t0 = blockIdx.y * 8;
    const int tid = threadIdx.x;            // 0..511

    __shared__ __align__(16) float xs[DET][8];
    __shared__ float Gt[DET];

    {
        int k = tid;
        float v;
        if (k == 0)       v = 0.5f;
        else if (k & 1) { float fk = (float)k; v = -2.0f / (9.869604401089358f * fk * fk); }
        else              v = 0.0f;
        Gt[k] = v;
    }

    const float* xb = x + (size_t)b * DET * NT;
    const int tt = tid & 7;
    const int mb = tid >> 3;                 // 0..63
    const int tg0 = t0 + tt;
    #pragma unroll
    for (int p = 0; p < 8; p++) {
        int m = mb + p * 64;
        xs[m][tt] = (tg0 < NT) ? xb[m * NT + tg0] : 0.0f;
    }
    __syncthreads();

    const int d = tid;
    float4 acc[2];
    {
        const float4* xd = (const float4*)xs[d];
        #pragma unroll
        for (int q = 0; q < 2; q++) {
            float4 v = xd[q];
            acc[q].x = 0.5f * v.x; acc[q].y = 0.5f * v.y;
            acc[q].z = 0.5f * v.z; acc[q].w = 0.5f * v.w;
        }
    }

    const int m0 = (d & 1) ^ 1;
    for (int j = 0; j < 256; j++) {
        int m = m0 + 2 * j;
        int k = d - m; k = (k < 0) ? -k : k;
        float gv = Gt[k];
        const float4* xm = (const float4*)xs[m];
        #pragma unroll
        for (int q = 0; q < 2; q++) {
            float4 v = xm[q];
            acc[q].x = fmaf(gv, v.x, acc[q].x);
            acc[q].y = fmaf(gv, v.y, acc[q].y);
            acc[q].z = fmaf(gv, v.z, acc[q].z);
            acc[q].w = fmaf(gv, v.w, acc[q].w);
        }
    }

    float vals[8];
    #pragma unroll
    for (int q = 0; q < 2; q++) {
        vals[q*4+0] = acc[q].x; vals[q*4+1] = acc[q].y;
        vals[q*4+2] = acc[q].z; vals[q*4+3] = acc[q].w;
    }
    #pragma unroll
    for (int r = 0; r < 8; r++) {
        int tg = t0 + r;
        if (tg < NT) g_xf[((size_t)b * NT + tg) * DET + d] = vals[r];
    }
}

// ---------------------------------------------------------------------------
// Kernel 1b: repack into padded forward+reversed fp16 quad-columns.
// ph=0 -> angles {0, 90}; ph in 1..89 -> {ph, 180-ph}.
// Forward: gF[i]=Gp[i], dF[i]=Gp[i+1]-Gp[i]. Reversed: gR[i]=Gp[767-i],
// dR[i]=Gp[766-i]-Gp[767-i]  (evaluates the interpolant at mirrored t with
// the SAME (i0, w)). Gp = zero-padded column; pads encode reference masking.
// ---------------------------------------------------------------------------
__global__ __launch_bounds__(256) void repack_kernel()
{
    const int b  = blockIdx.x;
    const int ph = blockIdx.y;
    const int t = (ph == 0) ? 0  : ph;
    const int u = (ph == 0) ? 90 : (180 - ph);

    const float* st = g_xf + ((size_t)b * NT + t) * DET;
    const float* su = g_xf + ((size_t)b * NT + u) * DET;
    uint4* dst = g_pk + ((size_t)b * NPH + ph) * CW;

    __shared__ float Gt[CW], Gu[CW];
    for (int i = threadIdx.x; i < CW; i += 256) {
        int d = i - 128;
        bool in = (d >= 0) && (d < DET);
        Gt[i] = in ? st[d] : 0.0f;
        Gu[i] = in ? su[d] : 0.0f;
    }
    __syncthreads();

    for (int i = threadIdx.x; i < CW; i += 256) {
        int ip  = (i + 1 < CW) ? i + 1 : CW - 1;   // clamped (entry 767 unused)
        int ir  = CW - 1 - i;
        int ir2 = (766 - i >= 0) ? 766 - i : 0;    // clamped (pad value 0 anyway)
        uint4 e;
        e.x = h2_to_u32(__floats2half2_rn(Gt[i],           Gu[i]));
        e.y = h2_to_u32(__floats2half2_rn(Gt[ip] - Gt[i],  Gu[ip] - Gu[i]));
        e.z = h2_to_u32(__floats2half2_rn(Gt[ir],          Gu[ir]));
        e.w = h2_to_u32(__floats2half2_rn(Gt[ir2] - Gt[ir], Gu[ir2] - Gu[ir]));
        dst[i] = e;
    }
}

// ---------------------------------------------------------------------------
// Kernel 2: backprojection over one quadrant; 4 mirror pixels x angle pair
// = 8 taps from 2 LDS.128 lookups.
// ---------------------------------------------------------------------------
#define TAPIDX(iy, i0, w)                                    \
    {   float _tm = __fadd_rd((iy), MAGIC);                  \
        (i0) = __float_as_int(_tm) & 0x3FF;                  \
        (w)  = (iy) - (_tm - MAGIC); }

__global__ __launch_bounds__(256, 7) void backproj_kernel(float* __restrict__ out)
{
    const int b  = blockIdx.z;
    const int x0 = blockIdx.x * 32;          // quadrant j tile [x0, x0+32), < 256
    const int y0 = blockIdx.y * 32;          // quadrant i tile [y0, y0+32), < 256
    const int tid = threadIdx.x;             // 0..255
    const int tx = tid & 31;
    const int ty = tid >> 5;                 // 0..7 ; i = y0+ty+8k, k<4

    __shared__ __align__(16) uint4 col[2][CW];
    __shared__ float2 cs[NPH];

    if (tid < NPH) {
        float rad = (float)tid * 0.017453292519943295f;
        float sv, cv;
        sincosf(rad, &sv, &cv);
        cs[tid] = make_float2(cv, sv);
    }

    const uint4* pkb = g_pk + (size_t)b * NPH * CW;

    #pragma unroll
    for (int r = 0; r < 3; r++) col[0][tid + r * 256] = pkb[tid + r * 256];
    __syncthreads();

    float accA[4], accB[4], accC[4], accD[4];
    #pragma unroll
    for (int k = 0; k < 4; k++) { accA[k]=0.f; accB[k]=0.f; accC[k]=0.f; accD[k]=0.f; }

    const float fx = (float)(x0 + tx) - 255.5f;   // = 256*u_j, always < 0
    const float fy = (float)(y0 + ty) - 255.5f;   // = 256*u_i (base), always < 0
    const float lim = 65408.0f;                   // (1 - 1/512) * 256^2
    const float MAGIC = 8388608.0f;               // 2^23

    // block-uniform circle skip (min |fx|,|fy| over the whole tile)
    const float fxmin = 255.5f - (float)(x0 + 31);
    const float fymin = 255.5f - (float)(y0 + 31);
    const bool active = (fxmin * fxmin + fymin * fymin) <= lim;

    for (int ph = 0; ph < NPH; ph++) {
        const int cur = ph & 1;
        {
            int pn = (ph + 1 < NPH) ? ph + 1 : ph;
            const uint4* src = pkb + (size_t)pn * CW;
            uint4* dstc = col[cur ^ 1];
            #pragma unroll
            for (int r = 0; r < 3; r++) dstc[tid + r * 256] = src[tid + r * 256];
        }

        if (active) {
            const uint4* cp = col[cur];
            if (ph == 0) {
                // lanes: low = angle 0, high = angle 90
                // j-lookup (k-independent): t = u_j -> fwd0 feeds A,D; rev0 feeds B,C
                float w; int i0; uint4 q;
                float iyj = fx + 383.5f;
                TAPIDX(iyj, i0, w); q = cp[i0];
                __half2 w2 = __float2half2_rn(w);
                float tf0 = __low2float(__hfma2(w2, u32_to_h2(q.y), u32_to_h2(q.x)));
                float tr0 = __low2float(__hfma2(w2, u32_to_h2(q.w), u32_to_h2(q.z)));
                #pragma unroll
                for (int k = 0; k < 4; k++) {
                    // i-lookup: t = u_i -> fwd90 feeds C,D; rev90 feeds A,B
                    float iyi = (fy + 8.0f * (float)k) + 383.5f;
                    TAPIDX(iyi, i0, w); q = cp[i0];
                    __half2 wk = __float2half2_rn(w);
                    float tf9 = __high2float(__hfma2(wk, u32_to_h2(q.y), u32_to_h2(q.x)));
                    float tr9 = __high2float(__hfma2(wk, u32_to_h2(q.w), u32_to_h2(q.z)));
                    accA[k] += tf0 + tr9;
                    accB[k] += tr0 + tr9;
                    accC[k] += tr0 + tf9;
                    accD[k] += tf0 + tf9;
                }
            } else {
                const float2 cst = cs[ph];
                const float c = cst.x, s = cst.y;
                const float base1 = fmaf(c, fx, fmaf(-s, fy, 383.5f)); // t1 = ujc - uis
                const float base2 = fmaf(c, fx, fmaf( s, fy, 383.5f)); // t2 = ujc + uis
                const float s8 = 8.0f * s;
                #pragma unroll
                for (int k = 0; k < 4; k++) {
                    float w; int i0; uint4 q;
                    // lookup 1: fwd -> (A@t, B@u); rev -> (C@t, D@u)
                    float iy1 = fmaf(-s8, (float)k, base1);
                    TAPIDX(iy1, i0, w); q = cp[i0];
                    {
                        __half2 w2 = __float2half2_rn(w);
                        __half2 vf = __hfma2(w2, u32_to_h2(q.y), u32_to_h2(q.x));
                        __half2 vr = __hfma2(w2, u32_to_h2(q.w), u32_to_h2(q.z));
                        accA[k] += __low2float(vf);
                        accB[k] += __high2float(vf);
                        accC[k] += __low2float(vr);
                        accD[k] += __high2float(vr);
                    }
                    // lookup 2: fwd -> (D@t, C@u); rev -> (B@t, A@u)
                    float iy2 = fmaf(s8, (float)k, base2);
                    TAPIDX(iy2, i0, w); q = cp[i0];
                    {
                        __half2 w2 = __float2half2_rn(w);
                        __half2 vf = __hfma2(w2, u32_to_h2(q.y), u32_to_h2(q.x));
                        __half2 vr = __hfma2(w2, u32_to_h2(q.w), u32_to_h2(q.z));
                        accD[k] += __low2float(vf);
                        accC[k] += __high2float(vf);
                        accB[k] += __low2float(vr);
                        accA[k] += __high2float(vr);
                    }
                }
            }
        }
        __syncthreads();
    }

    // epilogue: circle mask (symmetric across the quad) + pi/360 scale
    const float scale = 0.008726646259971648f;
    float* ob = out + (size_t)b * DET * DET;
    const int x1 = x0 + tx;
    const int x2 = 511 - x1;
    #pragma unroll
    for (int k = 0; k < 4; k++) {
        int   py  = y0 + ty + 8 * k;
        int   qy  = 511 - py;
        float fyk = fy + 8.0f * (float)k;
        float m   = ((fx * fx + fyk * fyk) <= lim) ? scale : 0.0f;
        ob[(size_t)py * DET + x1] = accA[k] * m;
        ob[(size_t)py * DET + x2] = accB[k] * m;
        ob[(size_t)qy * DET + x2] = accC[k] * m;
        ob[(size_t)qy * DET + x1] = accD[k] * m;
    }
}

extern "C" void kernel_launch(void* const* d_in, const int* in_sizes, int n_in,
                              void* d_out, int out_size)
{
    const float* x = (const float*)d_in[0];
    float* out = (float*)d_out;

    dim3 gf(NB, 23);          // 16 batches x ceil(180/8) angle tiles
    filter_kernel<<<gf, 512>>>(x);

    dim3 gr(NB, NPH);         // quad-column pack per (batch, phase)
    repack_kernel<<<gr, 256>>>();

    dim3 gb(8, 8, NB);        // quadrant: 8x8 tiles of 32x32, per batch
    backproj_kernel<<<gb, 256>>>(out);
}